// round 10
// baseline (speedup 1.0000x reference)
#include <cuda_runtime.h>

#define D       256
#define MMAX    5120
#define TOPK    32
#define INV_TAU 10.0f
#define PCOEF   0.25f      // BETA / (2*SIGMA^2)
#define PTHRESH 21.0f      // exact: >=32 cands with p<=1 dominate all p>21 (logit<-11)

#define QT 32              // queries per CTA tile
#define CT 128             // candidates per CTA tile
#define DT 64              // d-dim chunk (double-buffered)
#define KSTRIDE 68         // padded smem stride (floats): conflict-free LDS.128
#define NBC (MMAX / CT)    // 40 candidate blocks
#define CLSMAX  256
#define FQB 512            // filter blocks (512*256 float4 slots >= 125000)

__device__ int   g_count;
__device__ int   g_done;
__device__ int   g_ci[MMAX];
__device__ float g_cp[MMAX];
__device__ float g_logits[128 * MMAX];

__device__ __forceinline__ float neg_inf() { return __int_as_float(0xff800000); }

__device__ __forceinline__ void pdl_trigger() {
    asm volatile("griddepcontrol.launch_dependents;");
}
__device__ __forceinline__ void pdl_wait() {
    asm volatile("griddepcontrol.wait;" ::: "memory");
}

__device__ __forceinline__ unsigned long long fma2(unsigned long long a,
                                                   unsigned long long b,
                                                   unsigned long long c) {
    unsigned long long d;
    asm("fma.rn.f32x2 %0, %1, %2, %3;" : "=l"(d) : "l"(a), "l"(b), "l"(c));
    return d;
}

__device__ __forceinline__ void cp_async16(void* smem_dst, const void* gmem_src) {
    unsigned s = (unsigned)__cvta_generic_to_shared(smem_dst);
    asm volatile("cp.async.ca.shared.global [%0], [%1], 16;" :: "r"(s), "l"(gmem_src));
}
__device__ __forceinline__ void cp_async_commit() {
    asm volatile("cp.async.commit_group;");
}
template <int N>
__device__ __forceinline__ void cp_async_wait() {
    asm volatile("cp.async.wait_group %0;" :: "n"(N));
}

// Candidate filter (R7 shape: 512 blocks, 1 float4/thread, 1 global atomic per
// block). Triggers dependent launch (logits) at entry so it overlaps fully.
// g_count reset by topk tail.
__global__ __launch_bounds__(256) void filter_kernel(
        const float4* __restrict__ times4,
        const float* __restrict__ qtime, int N) {
    __shared__ int wbase[8];
    __shared__ int sbase;

    pdl_trigger();

    int bid = blockIdx.x, t = threadIdx.x;
    int lane = t & 31, w = t >> 5;

    int n4 = (N + 3) >> 2;
    int i = bid * 256 + t;
    bool ld = (i < n4);
    float4 tv;
    if (ld) tv = times4[i];
    float qt = __ldg(qtime);

    int keep = 0;
    float ps[4]; int is[4];
    if (ld) {
        float tt[4] = {tv.x, tv.y, tv.z, tv.w};
        #pragma unroll
        for (int c = 0; c < 4; c++) {
            if (i * 4 + c < N) {
                float dt = qt - tt[c];
                float p  = PCOEF * dt * dt;
                if (p <= PTHRESH) { ps[keep] = p; is[keep] = i * 4 + c; keep++; }
            }
        }
    }
    int x = keep;                                 // inclusive warp scan
    #pragma unroll
    for (int o = 1; o < 32; o <<= 1) {
        int y = __shfl_up_sync(0xffffffffu, x, o);
        if (lane >= o) x += y;
    }
    if (lane == 31) wbase[w] = x;
    __syncthreads();
    if (t < 32) {
        int wt = (t < 8) ? wbase[t] : 0;
        int xx = wt;
        #pragma unroll
        for (int o = 1; o < 8; o <<= 1) {
            int y = __shfl_up_sync(0xffffffffu, xx, o);
            if (t >= o) xx += y;
        }
        if (t < 8) wbase[t] = xx - wt;
        int btot = __shfl_sync(0xffffffffu, xx, 7);
        if (t == 0) sbase = (btot > 0) ? atomicAdd(&g_count, btot) : 0;
    }
    __syncthreads();
    int myoff = sbase + wbase[w] + x - keep;
    for (int k = 0; k < keep; k++) {
        int pos = myoff + k;
        if (pos < MMAX) { g_ci[pos] = is[k]; g_cp[pos] = ps[k]; }
    }
}

// logits[b][j] = (qn[b] . K[ci[j]]) / tau - p[j] for j < count, else -inf.
// PDL: normalizes its own q tile from raw `query` BEFORE griddepcontrol.wait,
// overlapping the filter kernel; then stages candidates + K via cp.async.
// 1D grid; cb = bid>>2, qb = bid&3 -> active CTAs contiguous, single wave.
__global__ __launch_bounds__(256) void logits_kernel(const float* __restrict__ Kbank,
                                                     const float* __restrict__ query) {
    extern __shared__ float smem[];
    float* qs = smem;                              // QT*D floats (32 KB)
    float* ks = smem + QT * D;                     // 2*CT*KSTRIDE floats (68 KB)
    int*   cis = (int*)(smem + QT * D + 2 * CT * KSTRIDE);

    int cb = blockIdx.x >> 2;
    int qb = blockIdx.x & 3;
    int cbase = cb * CT;
    int qbase = qb * QT;

    int t    = threadIdx.x;
    int w    = t >> 5;
    int lane = t & 31;
    int qrow0 = (w & 3) * 8;
    int c0    = (w >> 2) * 64 + lane;

    // ---- pre-wait prologue: normalize q rows (each warp: 4 rows) ----
    #pragma unroll
    for (int i = 0; i < 4; i++) {
        int row = w * 4 + i;
        const float* qr = query + (size_t)(qbase + row) * D + lane * 8;
        float4 a = *(const float4*)qr;
        float4 bq = *(const float4*)(qr + 4);
        float s = a.x*a.x + a.y*a.y + a.z*a.z + a.w*a.w
                + bq.x*bq.x + bq.y*bq.y + bq.z*bq.z + bq.w*bq.w;
        #pragma unroll
        for (int o = 16; o > 0; o >>= 1) s += __shfl_xor_sync(0xffffffffu, s, o);
        float inv = 1.0f / fmaxf(sqrtf(s), 1e-12f);
        float4 na = make_float4(a.x*inv, a.y*inv, a.z*inv, a.w*inv);
        float4 nb = make_float4(bq.x*inv, bq.y*inv, bq.z*inv, bq.w*inv);
        *(float4*)&qs[row * D + lane * 8]     = na;
        *(float4*)&qs[row * D + lane * 8 + 4] = nb;
    }

    // ---- wait for filter results ----
    pdl_wait();

    int count  = min(g_count, MMAX);
    int cnt256 = (count + 255) & ~255;
    if (cbase >= cnt256) { pdl_trigger(); return; }
    int nvalid = min(max(count - cbase, 0), CT);

    if (t < CT) cis[t] = (t < nvalid) ? g_ci[cbase + t] : 0;
    __syncthreads();

    unsigned long long acc2[8][2];
    #pragma unroll
    for (int i = 0; i < 8; i++) { acc2[i][0] = 0ull; acc2[i][1] = 0ull; }

    #pragma unroll
    for (int i = 0; i < 8; i++) {
        int idx = t + i * 256;
        int row = idx >> 4, col = (idx & 15) * 4;
        if (row < nvalid)
            cp_async16(&ks[row * KSTRIDE + col],
                       &Kbank[(size_t)cis[row] * D + col]);
    }
    cp_async_commit();

    #pragma unroll
    for (int s = 0; s < 4; s++) {
        if (s < 3) {
            int db = (s + 1) * DT, bb = (s + 1) & 1;
            #pragma unroll
            for (int i = 0; i < 8; i++) {
                int idx = t + i * 256;
                int row = idx >> 4, col = (idx & 15) * 4;
                if (row < nvalid)
                    cp_async16(&ks[bb * CT * KSTRIDE + row * KSTRIDE + col],
                               &Kbank[(size_t)cis[row] * D + db + col]);
            }
            cp_async_commit();
            cp_async_wait<1>();
        } else {
            cp_async_wait<0>();
        }
        __syncthreads();

        const float* kb = &ks[(s & 1) * CT * KSTRIDE];
        int db = s * DT;
        #pragma unroll
        for (int dd = 0; dd < DT; dd += 4) {
            ulonglong2 kv0 = *(const ulonglong2*)&kb[c0 * KSTRIDE + dd];
            ulonglong2 kv1 = *(const ulonglong2*)&kb[(c0 + 32) * KSTRIDE + dd];
            #pragma unroll
            for (int i = 0; i < 8; i++) {
                ulonglong2 qv = *(const ulonglong2*)&qs[(qrow0 + i) * D + db + dd];
                acc2[i][0] = fma2(qv.x, kv0.x, acc2[i][0]);
                acc2[i][0] = fma2(qv.y, kv0.y, acc2[i][0]);
                acc2[i][1] = fma2(qv.x, kv1.x, acc2[i][1]);
                acc2[i][1] = fma2(qv.y, kv1.y, acc2[i][1]);
            }
        }
        if (s < 3) __syncthreads();
    }

    pdl_trigger();                                 // let topk launch

    #pragma unroll
    for (int i = 0; i < 8; i++) {
        int qrow = qbase + qrow0 + i;
        #pragma unroll
        for (int j = 0; j < 2; j++) {
            int c = cbase + c0 + j * 32;
            float lo = __uint_as_float((unsigned)(acc2[i][j] & 0xffffffffull));
            float hi = __uint_as_float((unsigned)(acc2[i][j] >> 32));
            float dot = lo + hi;
            float val = (c < count) ? fmaf(dot, INV_TAU, -g_cp[c]) : neg_inf();
            g_logits[qrow * MMAX + c] = val;
        }
    }
}

// Exact top-32 per query: fused load/transform/lvl-0 hist, 11/11/10-bit radix,
// early exit to exact in-class rank, softmax, split V gather. PDL: zeroes its
// histogram before griddepcontrol.wait. Last block resets counters.
__global__ __launch_bounds__(1024) void topk_kernel(const float* __restrict__ Vbank,
                                                    float* __restrict__ out) {
    __shared__ unsigned su[MMAX];     // 20 KB
    __shared__ int hist[2048];        // 8 KB (aliased as gather-reduce buffer)
    __shared__ int wtot[32];
    __shared__ unsigned clsu[CLSMAX];
    __shared__ int   clsj[CLSMAX];
    __shared__ unsigned selu[TOPK];
    __shared__ int   selj[TOPK];
    __shared__ float attn[TOPK];
    __shared__ int s_b, s_above, s_cls, s_ngt, s_ncls;

    int b = blockIdx.x, t = threadIdx.x;
    int lane = t & 31, w = t >> 5;

    for (int i = t; i < 2048; i += 1024) hist[i] = 0;

    pdl_wait();
    __syncthreads();

    int count = min(g_count, MMAX);
    int cnt256 = (count + 255) & ~255;
    int n4 = cnt256 >> 2;

    for (int j4b = 0; j4b < n4; j4b += 1024) {
        int j4 = j4b + t;
        bool ok = j4 < n4;
        unsigned u[4];
        if (ok) {
            float4 v = *(const float4*)&g_logits[b * MMAX + j4 * 4];
            unsigned b0 = __float_as_uint(v.x), b1 = __float_as_uint(v.y);
            unsigned b2 = __float_as_uint(v.z), b3 = __float_as_uint(v.w);
            u[0] = (b0 & 0x80000000u) ? ~b0 : (b0 | 0x80000000u);
            u[1] = (b1 & 0x80000000u) ? ~b1 : (b1 | 0x80000000u);
            u[2] = (b2 & 0x80000000u) ? ~b2 : (b2 | 0x80000000u);
            u[3] = (b3 & 0x80000000u) ? ~b3 : (b3 | 0x80000000u);
            *(uint4*)&su[j4 * 4] = make_uint4(u[0], u[1], u[2], u[3]);
        }
        #pragma unroll
        for (int e = 0; e < 4; e++) {
            unsigned act = __ballot_sync(0xffffffffu, ok);
            if (ok) {
                unsigned bin = u[e] >> 21;
                unsigned peers = __match_any_sync(act, bin);
                if (lane == (__ffs(peers) - 1))
                    atomicAdd(&hist[bin], __popc(peers));
            }
        }
    }
    __syncthreads();

    const int shifts[3] = {21, 10, 0};
    const int nbits[3]  = {11, 11, 10};
    unsigned pmask = 0, pval = 0;
    int need = TOPK;

    for (int lvl = 0; lvl < 3; lvl++) {
        int shift = shifts[lvl];
        int nb = 1 << nbits[lvl];
        unsigned bmask = (unsigned)(nb - 1);
        int bpt = (nb > 1024) ? (nb >> 10) : 1;

        if (lvl > 0) {
            for (int i = t; i < nb; i += 1024) hist[i] = 0;
            __syncthreads();
            for (int jb = 0; jb < cnt256; jb += 1024) {
                int j = jb + t;
                unsigned u = (j < cnt256) ? su[j] : 0u;
                bool ok = (j < cnt256) && ((u & pmask) == pval);
                unsigned act = __ballot_sync(0xffffffffu, ok);
                if (ok) {
                    unsigned bin = (u >> shift) & bmask;
                    unsigned peers = __match_any_sync(act, bin);
                    if (lane == (__ffs(peers) - 1))
                        atomicAdd(&hist[bin], __popc(peers));
                }
            }
            __syncthreads();
        }

        int s = 0;
        int tb = t * bpt;
        #pragma unroll 2
        for (int i = 0; i < bpt; i++)
            if (tb + i < nb) s += hist[tb + i];
        int x = s;
        #pragma unroll
        for (int o = 1; o < 32; o <<= 1) {
            int y = __shfl_down_sync(0xffffffffu, x, o);
            if (lane + o < 32) x += y;
        }
        if (lane == 0) wtot[w] = x;
        __syncthreads();
        if (t < 32) {
            int ww = wtot[t];
            int xx = ww;
            #pragma unroll
            for (int o = 1; o < 32; o <<= 1) {
                int y = __shfl_down_sync(0xffffffffu, xx, o);
                if (t + o < 32) xx += y;
            }
            wtot[t] = xx - ww;
        }
        __syncthreads();
        int S = x + wtot[w];
        int Snext = S - s;

        if (S >= need && Snext < need) {
            int c = Snext;
            int bb = tb + bpt - 1;
            while (c + hist[bb] < need) { c += hist[bb]; bb--; }
            s_b = bb; s_above = c; s_cls = hist[bb];
        }
        __syncthreads();
        pval  |= ((unsigned)s_b) << shift;
        pmask |= bmask << shift;
        need  -= s_above;
        if (s_cls <= CLSMAX) break;
        __syncthreads();
    }

    if (t == 0) { s_ngt = 0; s_ncls = 0; }
    __syncthreads();
    for (int j = t; j < cnt256; j += 1024) {
        unsigned u = su[j];
        unsigned m = u & pmask;
        if (m > pval) {
            int p = atomicAdd(&s_ngt, 1);
            selu[p] = u; selj[p] = j;
        } else if (m == pval) {
            int p = atomicAdd(&s_ncls, 1);
            if (p < CLSMAX) { clsu[p] = u; clsj[p] = j; }
        }
    }
    __syncthreads();

    int ngt  = s_ngt;
    int clsN = min(s_ncls, CLSMAX);
    if (t < clsN) {
        unsigned ui = clsu[t]; int ji = clsj[t];
        int rank = 0;
        for (int j = 0; j < clsN; j++) {
            unsigned uj = clsu[j]; int jj = clsj[j];
            rank += (uj > ui || (uj == ui && jj < ji)) ? 1 : 0;
        }
        if (rank < need) { selu[ngt + rank] = ui; selj[ngt + rank] = ji; }
    }
    __syncthreads();

    if (t < 32) {
        unsigned u = selu[t];
        unsigned bits = (u & 0x80000000u) ? (u ^ 0x80000000u) : ~u;
        float v = __int_as_float(bits);
        float m = v;
        #pragma unroll
        for (int o = 16; o > 0; o >>= 1) m = fmaxf(m, __shfl_xor_sync(0xffffffffu, m, o));
        float e = expf(v - m);
        float sm = e;
        #pragma unroll
        for (int o = 16; o > 0; o >>= 1) sm += __shfl_xor_sync(0xffffffffu, sm, o);
        attn[t] = e / sm;
        selj[t] = g_ci[selj[t]];
    }
    __syncthreads();

    float* red = (float*)hist;
    int kg = t >> 8, d = t & 255;
    float part = 0.0f;
    #pragma unroll
    for (int k = 0; k < 8; k++) {
        int kk = kg * 8 + k;
        part = fmaf(attn[kk], Vbank[(size_t)selj[kk] * D + d], part);
    }
    red[kg * 256 + d] = part;
    __syncthreads();
    if (t < 256)
        out[b * D + t] = (red[t] + red[256 + t]) + (red[512 + t] + red[768 + t]);
    __syncthreads();

    if (t == 0) {
        int ticket = atomicAdd(&g_done, 1);
        if (ticket == (int)gridDim.x - 1) { g_done = 0; g_count = 0; }
    }
}

extern "C" void kernel_launch(void* const* d_in, const int* in_sizes, int n_in,
                              void* d_out, int out_size) {
    const float* query = (const float*)d_in[0];
    const float* Kbank = (const float*)d_in[1];
    const float* Vbank = (const float*)d_in[2];
    const float* times = (const float*)d_in[3];
    const float* qtime = (const float*)d_in[4];
    float* out = (float*)d_out;

    int N  = in_sizes[3];       // 500000

    static int smem_set = 0;
    int dyn_smem = (QT * D + 2 * CT * KSTRIDE) * 4 + CT * 4;
    if (!smem_set) {
        cudaFuncSetAttribute(logits_kernel,
                             cudaFuncAttributeMaxDynamicSharedMemorySize, dyn_smem);
        smem_set = 1;
    }

    // K1: filter (triggers dependents at entry)
    {
        cudaLaunchConfig_t cfg = {};
        cfg.gridDim = dim3(FQB);
        cfg.blockDim = dim3(256);
        cudaLaunchKernelEx(&cfg, filter_kernel, (const float4*)times, qtime, N);
    }
    // K2: logits (PDL dependent of filter)
    {
        cudaLaunchConfig_t cfg = {};
        cfg.gridDim = dim3(NBC * 4);
        cfg.blockDim = dim3(256);
        cfg.dynamicSmemBytes = dyn_smem;
        cudaLaunchAttribute attr[1];
        attr[0].id = cudaLaunchAttributeProgrammaticStreamSerialization;
        attr[0].val.programmaticStreamSerializationAllowed = 1;
        cfg.attrs = attr;
        cfg.numAttrs = 1;
        cudaLaunchKernelEx(&cfg, logits_kernel, Kbank, query);
    }
    // K3: topk (PDL dependent of logits)
    {
        cudaLaunchConfig_t cfg = {};
        cfg.gridDim = dim3(128);
        cfg.blockDim = dim3(1024);
        cudaLaunchAttribute attr[1];
        attr[0].id = cudaLaunchAttributeProgrammaticStreamSerialization;
        attr[0].val.programmaticStreamSerializationAllowed = 1;
        cfg.attrs = attr;
        cfg.numAttrs = 1;
        cudaLaunchKernelEx(&cfg, topk_kernel, Vbank, out);
    }
}

// round 11
// speedup vs baseline: 1.3727x; 1.3727x over previous
#include <cuda_runtime.h>

#define D       256
#define MMAX    5120
#define TOPK    32
#define INV_TAU 10.0f
#define PCOEF   0.25f      // BETA / (2*SIGMA^2)
#define PTHRESH 21.0f      // exact: >=32 cands with p<=1 dominate all p>21 (logit<-11)

#define QT 32              // queries per CTA tile
#define CT 128             // candidates per CTA tile
#define DT 64              // d-dim chunk (double-buffered)
#define KSTRIDE 68         // padded smem stride (floats): conflict-free LDS.128
#define NBC (MMAX / CT)    // 40 candidate blocks
#define CLSMAX  256
#define FQB 512            // filter blocks (512*256 float4 slots >= 125000)

__device__ int   g_count;
__device__ int   g_done;
__device__ int   g_ci[MMAX];
__device__ float g_cp[MMAX];
__device__ float g_qn[128 * D];
__device__ float g_logits[128 * MMAX];

__device__ __forceinline__ float neg_inf() { return __int_as_float(0xff800000); }

__device__ __forceinline__ void pdl_trigger() {
    asm volatile("griddepcontrol.launch_dependents;");
}
__device__ __forceinline__ void pdl_wait() {
    asm volatile("griddepcontrol.wait;" ::: "memory");
}

__device__ __forceinline__ unsigned long long fma2(unsigned long long a,
                                                   unsigned long long b,
                                                   unsigned long long c) {
    unsigned long long d;
    asm("fma.rn.f32x2 %0, %1, %2, %3;" : "=l"(d) : "l"(a), "l"(b), "l"(c));
    return d;
}

__device__ __forceinline__ void cp_async16(void* smem_dst, const void* gmem_src) {
    unsigned s = (unsigned)__cvta_generic_to_shared(smem_dst);
    asm volatile("cp.async.ca.shared.global [%0], [%1], 16;" :: "r"(s), "l"(gmem_src));
}
__device__ __forceinline__ void cp_async_commit() {
    asm volatile("cp.async.commit_group;");
}
template <int N>
__device__ __forceinline__ void cp_async_wait() {
    asm volatile("cp.async.wait_group %0;" :: "n"(N));
}

// Fused: candidate filter (all blocks, loads issued first) + q-normalize
// (blocks 0..127, overlapped with the in-flight filter loads).
// One global atomic per block. Triggers dependents at the END (drain overlap
// only -> no SM contention). g_count reset by topk tail.
__global__ __launch_bounds__(256) void filter_qnorm_kernel(
        const float4* __restrict__ times4,
        const float* __restrict__ qtime,
        const float* __restrict__ query, int N) {
    __shared__ float ws[8];
    __shared__ int   wbase[8];
    __shared__ int   sbase;

    int bid = blockIdx.x, t = threadIdx.x;
    int lane = t & 31, w = t >> 5;

    // issue filter load immediately
    int n4 = (N + 3) >> 2;
    int i = bid * 256 + t;
    bool ld = (i < n4);
    float4 tv;
    if (ld) tv = times4[i];
    float qt = __ldg(qtime);

    // qnorm (blocks 0..127) — overlaps with in-flight times4 loads
    if (bid < 128) {
        int b = bid;
        float v = query[b * D + t];
        float s = v * v;
        #pragma unroll
        for (int o = 16; o > 0; o >>= 1) s += __shfl_xor_sync(0xffffffffu, s, o);
        if (lane == 0) ws[w] = s;
        __syncthreads();
        if (t < 32) {
            float x = (t < 8) ? ws[t] : 0.0f;
            #pragma unroll
            for (int o = 4; o > 0; o >>= 1) x += __shfl_xor_sync(0xffffffffu, x, o);
            if (t == 0) ws[0] = x;
        }
        __syncthreads();
        float norm = fmaxf(sqrtf(ws[0]), 1e-12f);
        g_qn[b * D + t] = v / norm;
    }

    // filter: predicate + warp scan + block aggregate (1 atomic per block)
    int keep = 0;
    float ps[4]; int is[4];
    if (ld) {
        float tt[4] = {tv.x, tv.y, tv.z, tv.w};
        #pragma unroll
        for (int c = 0; c < 4; c++) {
            if (i * 4 + c < N) {
                float dt = qt - tt[c];
                float p  = PCOEF * dt * dt;
                if (p <= PTHRESH) { ps[keep] = p; is[keep] = i * 4 + c; keep++; }
            }
        }
    }
    int x = keep;                                 // inclusive warp scan
    #pragma unroll
    for (int o = 1; o < 32; o <<= 1) {
        int y = __shfl_up_sync(0xffffffffu, x, o);
        if (lane >= o) x += y;
    }
    if (lane == 31) wbase[w] = x;
    __syncthreads();
    if (t < 32) {
        int wt = (t < 8) ? wbase[t] : 0;
        int xx = wt;
        #pragma unroll
        for (int o = 1; o < 8; o <<= 1) {
            int y = __shfl_up_sync(0xffffffffu, xx, o);
            if (t >= o) xx += y;
        }
        if (t < 8) wbase[t] = xx - wt;
        int btot = __shfl_sync(0xffffffffu, xx, 7);
        if (t == 0) sbase = (btot > 0) ? atomicAdd(&g_count, btot) : 0;
    }
    __syncthreads();
    int myoff = sbase + wbase[w] + x - keep;
    for (int k = 0; k < keep; k++) {
        int pos = myoff + k;
        if (pos < MMAX) { g_ci[pos] = is[k]; g_cp[pos] = ps[k]; }
    }

    pdl_trigger();                                // drain-overlap only
}

// logits[b][j] = (qn[b] . K[ci[j]]) / tau - p[j] for j < count, else -inf.
// 1D grid; cb = bid>>2, qb = bid&3 so active CTAs occupy contiguous low bids
// -> single wave. QT=32 x CT=128, 256 threads, 8q x 2c register block,
// f32x2 FMA, K double-buffered via cp.async. PDL both ways.
__global__ __launch_bounds__(256) void logits_kernel(const float* __restrict__ Kbank) {
    extern __shared__ float smem[];
    float* qs = smem;                              // QT*D floats (32 KB)
    float* ks = smem + QT * D;                     // 2*CT*KSTRIDE floats (68 KB)
    int*   cis = (int*)(smem + QT * D + 2 * CT * KSTRIDE);

    int cb = blockIdx.x >> 2;
    int qb = blockIdx.x & 3;
    int cbase = cb * CT;
    int qbase = qb * QT;

    int t    = threadIdx.x;
    int w    = t >> 5;
    int lane = t & 31;
    int qrow0 = (w & 3) * 8;
    int c0    = (w >> 2) * 64 + lane;

    pdl_wait();                                    // filter results + g_qn

    int count  = min(g_count, MMAX);
    int cnt256 = (count + 255) & ~255;
    if (cbase >= cnt256) { pdl_trigger(); return; }
    int nvalid = min(max(count - cbase, 0), CT);

    #pragma unroll
    for (int i = 0; i < 8; i++) {
        int idx = t + i * 256;
        int row = idx >> 6, col = (idx & 63) * 4;
        *(float4*)&qs[row * D + col] =
            *(const float4*)&g_qn[(qbase + row) * D + col];
    }
    if (t < CT) cis[t] = (t < nvalid) ? g_ci[cbase + t] : 0;
    __syncthreads();

    unsigned long long acc2[8][2];
    #pragma unroll
    for (int i = 0; i < 8; i++) { acc2[i][0] = 0ull; acc2[i][1] = 0ull; }

    #pragma unroll
    for (int i = 0; i < 8; i++) {
        int idx = t + i * 256;
        int row = idx >> 4, col = (idx & 15) * 4;
        if (row < nvalid)
            cp_async16(&ks[row * KSTRIDE + col],
                       &Kbank[(size_t)cis[row] * D + col]);
    }
    cp_async_commit();

    #pragma unroll
    for (int s = 0; s < 4; s++) {
        if (s < 3) {
            int db = (s + 1) * DT, bb = (s + 1) & 1;
            #pragma unroll
            for (int i = 0; i < 8; i++) {
                int idx = t + i * 256;
                int row = idx >> 4, col = (idx & 15) * 4;
                if (row < nvalid)
                    cp_async16(&ks[bb * CT * KSTRIDE + row * KSTRIDE + col],
                               &Kbank[(size_t)cis[row] * D + db + col]);
            }
            cp_async_commit();
            cp_async_wait<1>();
        } else {
            cp_async_wait<0>();
        }
        __syncthreads();

        const float* kb = &ks[(s & 1) * CT * KSTRIDE];
        int db = s * DT;
        #pragma unroll
        for (int dd = 0; dd < DT; dd += 4) {
            ulonglong2 kv0 = *(const ulonglong2*)&kb[c0 * KSTRIDE + dd];
            ulonglong2 kv1 = *(const ulonglong2*)&kb[(c0 + 32) * KSTRIDE + dd];
            #pragma unroll
            for (int i = 0; i < 8; i++) {
                ulonglong2 qv = *(const ulonglong2*)&qs[(qrow0 + i) * D + db + dd];
                acc2[i][0] = fma2(qv.x, kv0.x, acc2[i][0]);
                acc2[i][0] = fma2(qv.y, kv0.y, acc2[i][0]);
                acc2[i][1] = fma2(qv.x, kv1.x, acc2[i][1]);
                acc2[i][1] = fma2(qv.y, kv1.y, acc2[i][1]);
            }
        }
        if (s < 3) __syncthreads();
    }

    #pragma unroll
    for (int i = 0; i < 8; i++) {
        int qrow = qbase + qrow0 + i;
        #pragma unroll
        for (int j = 0; j < 2; j++) {
            int c = cbase + c0 + j * 32;
            float lo = __uint_as_float((unsigned)(acc2[i][j] & 0xffffffffull));
            float hi = __uint_as_float((unsigned)(acc2[i][j] >> 32));
            float dot = lo + hi;
            float val = (c < count) ? fmaf(dot, INV_TAU, -g_cp[c]) : neg_inf();
            g_logits[qrow * MMAX + c] = val;
        }
    }

    pdl_trigger();                                 // drain-overlap for topk
}

// Exact top-32 per query: fused load/transform/lvl-0 hist, 11/11/10-bit radix,
// early exit to exact in-class rank, softmax, split V gather. PDL: zeroes its
// histogram before griddepcontrol.wait. Last block resets counters.
__global__ __launch_bounds__(1024) void topk_kernel(const float* __restrict__ Vbank,
                                                    float* __restrict__ out) {
    __shared__ unsigned su[MMAX];     // 20 KB
    __shared__ int hist[2048];        // 8 KB (aliased as gather-reduce buffer)
    __shared__ int wtot[32];
    __shared__ unsigned clsu[CLSMAX];
    __shared__ int   clsj[CLSMAX];
    __shared__ unsigned selu[TOPK];
    __shared__ int   selj[TOPK];
    __shared__ float attn[TOPK];
    __shared__ int s_b, s_above, s_cls, s_ngt, s_ncls;

    int b = blockIdx.x, t = threadIdx.x;
    int lane = t & 31, w = t >> 5;

    for (int i = t; i < 2048; i += 1024) hist[i] = 0;

    pdl_wait();
    __syncthreads();

    int count = min(g_count, MMAX);
    int cnt256 = (count + 255) & ~255;
    int n4 = cnt256 >> 2;

    for (int j4b = 0; j4b < n4; j4b += 1024) {
        int j4 = j4b + t;
        bool ok = j4 < n4;
        unsigned u[4];
        if (ok) {
            float4 v = *(const float4*)&g_logits[b * MMAX + j4 * 4];
            unsigned b0 = __float_as_uint(v.x), b1 = __float_as_uint(v.y);
            unsigned b2 = __float_as_uint(v.z), b3 = __float_as_uint(v.w);
            u[0] = (b0 & 0x80000000u) ? ~b0 : (b0 | 0x80000000u);
            u[1] = (b1 & 0x80000000u) ? ~b1 : (b1 | 0x80000000u);
            u[2] = (b2 & 0x80000000u) ? ~b2 : (b2 | 0x80000000u);
            u[3] = (b3 & 0x80000000u) ? ~b3 : (b3 | 0x80000000u);
            *(uint4*)&su[j4 * 4] = make_uint4(u[0], u[1], u[2], u[3]);
        }
        #pragma unroll
        for (int e = 0; e < 4; e++) {
            unsigned act = __ballot_sync(0xffffffffu, ok);
            if (ok) {
                unsigned bin = u[e] >> 21;
                unsigned peers = __match_any_sync(act, bin);
                if (lane == (__ffs(peers) - 1))
                    atomicAdd(&hist[bin], __popc(peers));
            }
        }
    }
    __syncthreads();

    const int shifts[3] = {21, 10, 0};
    const int nbits[3]  = {11, 11, 10};
    unsigned pmask = 0, pval = 0;
    int need = TOPK;

    for (int lvl = 0; lvl < 3; lvl++) {
        int shift = shifts[lvl];
        int nb = 1 << nbits[lvl];
        unsigned bmask = (unsigned)(nb - 1);
        int bpt = (nb > 1024) ? (nb >> 10) : 1;

        if (lvl > 0) {
            for (int i = t; i < nb; i += 1024) hist[i] = 0;
            __syncthreads();
            for (int jb = 0; jb < cnt256; jb += 1024) {
                int j = jb + t;
                unsigned u = (j < cnt256) ? su[j] : 0u;
                bool ok = (j < cnt256) && ((u & pmask) == pval);
                unsigned act = __ballot_sync(0xffffffffu, ok);
                if (ok) {
                    unsigned bin = (u >> shift) & bmask;
                    unsigned peers = __match_any_sync(act, bin);
                    if (lane == (__ffs(peers) - 1))
                        atomicAdd(&hist[bin], __popc(peers));
                }
            }
            __syncthreads();
        }

        int s = 0;
        int tb = t * bpt;
        #pragma unroll 2
        for (int i = 0; i < bpt; i++)
            if (tb + i < nb) s += hist[tb + i];
        int x = s;
        #pragma unroll
        for (int o = 1; o < 32; o <<= 1) {
            int y = __shfl_down_sync(0xffffffffu, x, o);
            if (lane + o < 32) x += y;
        }
        if (lane == 0) wtot[w] = x;
        __syncthreads();
        if (t < 32) {
            int ww = wtot[t];
            int xx = ww;
            #pragma unroll
            for (int o = 1; o < 32; o <<= 1) {
                int y = __shfl_down_sync(0xffffffffu, xx, o);
                if (t + o < 32) xx += y;
            }
            wtot[t] = xx - ww;
        }
        __syncthreads();
        int S = x + wtot[w];
        int Snext = S - s;

        if (S >= need && Snext < need) {
            int c = Snext;
            int bb = tb + bpt - 1;
            while (c + hist[bb] < need) { c += hist[bb]; bb--; }
            s_b = bb; s_above = c; s_cls = hist[bb];
        }
        __syncthreads();
        pval  |= ((unsigned)s_b) << shift;
        pmask |= bmask << shift;
        need  -= s_above;
        if (s_cls <= CLSMAX) break;
        __syncthreads();
    }

    if (t == 0) { s_ngt = 0; s_ncls = 0; }
    __syncthreads();
    for (int j = t; j < cnt256; j += 1024) {
        unsigned u = su[j];
        unsigned m = u & pmask;
        if (m > pval) {
            int p = atomicAdd(&s_ngt, 1);
            selu[p] = u; selj[p] = j;
        } else if (m == pval) {
            int p = atomicAdd(&s_ncls, 1);
            if (p < CLSMAX) { clsu[p] = u; clsj[p] = j; }
        }
    }
    __syncthreads();

    int ngt  = s_ngt;
    int clsN = min(s_ncls, CLSMAX);
    if (t < clsN) {
        unsigned ui = clsu[t]; int ji = clsj[t];
        int rank = 0;
        for (int j = 0; j < clsN; j++) {
            unsigned uj = clsu[j]; int jj = clsj[j];
            rank += (uj > ui || (uj == ui && jj < ji)) ? 1 : 0;
        }
        if (rank < need) { selu[ngt + rank] = ui; selj[ngt + rank] = ji; }
    }
    __syncthreads();

    if (t < 32) {
        unsigned u = selu[t];
        unsigned bits = (u & 0x80000000u) ? (u ^ 0x80000000u) : ~u;
        float v = __int_as_float(bits);
        float m = v;
        #pragma unroll
        for (int o = 16; o > 0; o >>= 1) m = fmaxf(m, __shfl_xor_sync(0xffffffffu, m, o));
        float e = expf(v - m);
        float sm = e;
        #pragma unroll
        for (int o = 16; o > 0; o >>= 1) sm += __shfl_xor_sync(0xffffffffu, sm, o);
        attn[t] = e / sm;
        selj[t] = g_ci[selj[t]];
    }
    __syncthreads();

    float* red = (float*)hist;
    int kg = t >> 8, d = t & 255;
    float part = 0.0f;
    #pragma unroll
    for (int k = 0; k < 8; k++) {
        int kk = kg * 8 + k;
        part = fmaf(attn[kk], Vbank[(size_t)selj[kk] * D + d], part);
    }
    red[kg * 256 + d] = part;
    __syncthreads();
    if (t < 256)
        out[b * D + t] = (red[t] + red[256 + t]) + (red[512 + t] + red[768 + t]);
    __syncthreads();

    if (t == 0) {
        int ticket = atomicAdd(&g_done, 1);
        if (ticket == (int)gridDim.x - 1) { g_done = 0; g_count = 0; }
    }
}

extern "C" void kernel_launch(void* const* d_in, const int* in_sizes, int n_in,
                              void* d_out, int out_size) {
    const float* query = (const float*)d_in[0];
    const float* Kbank = (const float*)d_in[1];
    const float* Vbank = (const float*)d_in[2];
    const float* times = (const float*)d_in[3];
    const float* qtime = (const float*)d_in[4];
    float* out = (float*)d_out;

    int N  = in_sizes[3];       // 500000

    static int smem_set = 0;
    int dyn_smem = (QT * D + 2 * CT * KSTRIDE) * 4 + CT * 4;
    if (!smem_set) {
        cudaFuncSetAttribute(logits_kernel,
                             cudaFuncAttributeMaxDynamicSharedMemorySize, dyn_smem);
        smem_set = 1;
    }

    // K1: filter+qnorm (triggers dependents at drain)
    {
        cudaLaunchConfig_t cfg = {};
        cfg.gridDim = dim3(FQB);
        cfg.blockDim = dim3(256);
        cudaLaunchKernelEx(&cfg, filter_qnorm_kernel,
                           (const float4*)times, qtime, query, N);
    }
    // K2: logits (PDL dependent of filter)
    {
        cudaLaunchConfig_t cfg = {};
        cfg.gridDim = dim3(NBC * 4);
        cfg.blockDim = dim3(256);
        cfg.dynamicSmemBytes = dyn_smem;
        cudaLaunchAttribute attr[1];
        attr[0].id = cudaLaunchAttributeProgrammaticStreamSerialization;
        attr[0].val.programmaticStreamSerializationAllowed = 1;
        cfg.attrs = attr;
        cfg.numAttrs = 1;
        cudaLaunchKernelEx(&cfg, logits_kernel, Kbank);
    }
    // K3: topk (PDL dependent of logits)
    {
        cudaLaunchConfig_t cfg = {};
        cfg.gridDim = dim3(128);
        cfg.blockDim = dim3(1024);
        cudaLaunchAttribute attr[1];
        attr[0].id = cudaLaunchAttributeProgrammaticStreamSerialization;
        attr[0].val.programmaticStreamSerializationAllowed = 1;
        cfg.attrs = attr;
        cfg.numAttrs = 1;
        cudaLaunchKernelEx(&cfg, topk_kernel, Vbank, out);
    }
}

// round 12
// speedup vs baseline: 1.3872x; 1.0106x over previous
#include <cuda_runtime.h>

#define D       256
#define MMAX    5120
#define TOPK    32
#define INV_TAU 10.0f
#define PCOEF   0.25f      // BETA / (2*SIGMA^2)
#define PTHRESH 21.0f      // exact: >=32 cands with p<=1 dominate all p>21 (logit<-11)

#define QT 32              // queries per CTA tile
#define CT 128             // candidates per CTA tile
#define DT 64              // d-dim chunk (double-buffered)
#define KSTRIDE 68         // padded smem stride (floats)
#define NBC (MMAX / CT)    // 40 candidate blocks
#define GRID1 (NBC * 4)    // 160 CTAs for fused kernel
#define CLSMAX  256

__device__ int   g_count;
__device__ int   g_done;
__device__ int   g_bar;
__device__ int   g_ci[MMAX];
__device__ float g_cp[MMAX];
__device__ float g_qn[128 * D];
__device__ float g_logits[128 * MMAX];

__device__ __forceinline__ float neg_inf() { return __int_as_float(0xff800000); }

__device__ __forceinline__ unsigned long long fma2(unsigned long long a,
                                                   unsigned long long b,
                                                   unsigned long long c) {
    unsigned long long d;
    asm("fma.rn.f32x2 %0, %1, %2, %3;" : "=l"(d) : "l"(a), "l"(b), "l"(c));
    return d;
}

__device__ __forceinline__ void cp_async16(void* smem_dst, const void* gmem_src) {
    unsigned s = (unsigned)__cvta_generic_to_shared(smem_dst);
    asm volatile("cp.async.ca.shared.global [%0], [%1], 16;" :: "r"(s), "l"(gmem_src));
}
__device__ __forceinline__ void cp_async_commit() {
    asm volatile("cp.async.commit_group;");
}
template <int N>
__device__ __forceinline__ void cp_async_wait() {
    asm volatile("cp.async.wait_group %0;" :: "n"(N));
}

// Fused: [filter + qnorm]  -> device-wide barrier ->  [logits].
// 160 CTAs x 256 threads, all co-resident (103KB smem, 2-CTA/SM capacity), so
// the spin barrier cannot deadlock. One global atomic per CTA for compaction.
// g_count/g_bar reset by topk tail.
__global__ __launch_bounds__(256) void fused_filter_logits_kernel(
        const float* __restrict__ Kbank,
        const float* __restrict__ query,
        const float4* __restrict__ times4,
        const float* __restrict__ qtime, int N) {
    extern __shared__ float smem[];
    float* qs = smem;                              // QT*D floats (32 KB)
    float* ks = smem + QT * D;                     // 2*CT*KSTRIDE floats (68 KB)
    int*   cis = (int*)(smem + QT * D + 2 * CT * KSTRIDE);
    __shared__ float ws[8];
    __shared__ int   wbase[8];
    __shared__ int   sbase;

    int bid = blockIdx.x, t = threadIdx.x;
    int lane = t & 31, w = t >> 5;

    // ================= Phase A: filter + qnorm =================
    {
        int n4 = (N + 3) >> 2;
        // front-batch 4 independent float4 loads (CTA covers 1024 consecutive)
        float4 tv[4]; bool ld[4]; int ibase = bid * 1024 + t;
        #pragma unroll
        for (int k = 0; k < 4; k++) {
            int i = ibase + k * 256;
            ld[k] = (i < n4);
            if (ld[k]) tv[k] = times4[i];
        }
        float qt = __ldg(qtime);

        // qnorm overlapped with in-flight loads (CTAs 0..127, 256 thr = D)
        if (bid < 128) {
            float v = query[bid * D + t];
            float s = v * v;
            #pragma unroll
            for (int o = 16; o > 0; o >>= 1) s += __shfl_xor_sync(0xffffffffu, s, o);
            if (lane == 0) ws[w] = s;
            __syncthreads();
            if (t < 32) {
                float x = (t < 8) ? ws[t] : 0.0f;
                #pragma unroll
                for (int o = 4; o > 0; o >>= 1) x += __shfl_xor_sync(0xffffffffu, x, o);
                if (t == 0) ws[0] = x;
            }
            __syncthreads();
            float norm = fmaxf(sqrtf(ws[0]), 1e-12f);
            g_qn[bid * D + t] = v / norm;
        }

        // predicate all 16 slots into one keep-list (avg ~0.15 kept/thread)
        int keep = 0;
        float ps[16]; int is[16];
        #pragma unroll
        for (int k = 0; k < 4; k++) {
            if (ld[k]) {
                int i = ibase + k * 256;
                float tt[4] = {tv[k].x, tv[k].y, tv[k].z, tv[k].w};
                #pragma unroll
                for (int c = 0; c < 4; c++) {
                    if (i * 4 + c < N) {
                        float dt = qt - tt[c];
                        float p  = PCOEF * dt * dt;
                        if (p <= PTHRESH) { ps[keep] = p; is[keep] = i * 4 + c; keep++; }
                    }
                }
            }
        }
        int x = keep;                             // inclusive warp scan
        #pragma unroll
        for (int o = 1; o < 32; o <<= 1) {
            int y = __shfl_up_sync(0xffffffffu, x, o);
            if (lane >= o) x += y;
        }
        if (lane == 31) wbase[w] = x;
        __syncthreads();
        if (t < 32) {
            int wt = (t < 8) ? wbase[t] : 0;
            int xx = wt;
            #pragma unroll
            for (int o = 1; o < 8; o <<= 1) {
                int y = __shfl_up_sync(0xffffffffu, xx, o);
                if (t >= o) xx += y;
            }
            if (t < 8) wbase[t] = xx - wt;
            int btot = __shfl_sync(0xffffffffu, xx, 7);
            if (t == 0) sbase = (btot > 0) ? atomicAdd(&g_count, btot) : 0;
        }
        __syncthreads();
        int myoff = sbase + wbase[w] + x - keep;
        for (int k = 0; k < keep; k++) {
            int pos = myoff + k;
            if (pos < MMAX) { g_ci[pos] = is[k]; g_cp[pos] = ps[k]; }
        }
    }

    // ================= device-wide barrier =================
    __threadfence();
    __syncthreads();
    if (t == 0) {
        atomicAdd(&g_bar, 1);
        while (*(volatile int*)&g_bar < GRID1) { }
        __threadfence();
    }
    __syncthreads();

    // ================= Phase B: logits =================
    int cb = bid >> 2;
    int qb = bid & 3;
    int cbase = cb * CT;
    int qbase = qb * QT;
    int qrow0 = (w & 3) * 8;
    int c0    = (w >> 2) * 64 + lane;

    int count  = min(g_count, MMAX);
    int cnt256 = (count + 255) & ~255;
    if (cbase >= cnt256) return;
    int nvalid = min(max(count - cbase, 0), CT);

    #pragma unroll
    for (int i = 0; i < 8; i++) {
        int idx = t + i * 256;
        int row = idx >> 6, col = (idx & 63) * 4;
        *(float4*)&qs[row * D + col] =
            *(const float4*)&g_qn[(qbase + row) * D + col];
    }
    if (t < CT) cis[t] = (t < nvalid) ? g_ci[cbase + t] : 0;
    __syncthreads();

    unsigned long long acc2[8][2];
    #pragma unroll
    for (int i = 0; i < 8; i++) { acc2[i][0] = 0ull; acc2[i][1] = 0ull; }

    #pragma unroll
    for (int i = 0; i < 8; i++) {
        int idx = t + i * 256;
        int row = idx >> 4, col = (idx & 15) * 4;
        if (row < nvalid)
            cp_async16(&ks[row * KSTRIDE + col],
                       &Kbank[(size_t)cis[row] * D + col]);
    }
    cp_async_commit();

    #pragma unroll
    for (int s = 0; s < 4; s++) {
        if (s < 3) {
            int db = (s + 1) * DT, bb = (s + 1) & 1;
            #pragma unroll
            for (int i = 0; i < 8; i++) {
                int idx = t + i * 256;
                int row = idx >> 4, col = (idx & 15) * 4;
                if (row < nvalid)
                    cp_async16(&ks[bb * CT * KSTRIDE + row * KSTRIDE + col],
                               &Kbank[(size_t)cis[row] * D + db + col]);
            }
            cp_async_commit();
            cp_async_wait<1>();
        } else {
            cp_async_wait<0>();
        }
        __syncthreads();

        const float* kb = &ks[(s & 1) * CT * KSTRIDE];
        int db = s * DT;
        #pragma unroll
        for (int dd = 0; dd < DT; dd += 4) {
            ulonglong2 kv0 = *(const ulonglong2*)&kb[c0 * KSTRIDE + dd];
            ulonglong2 kv1 = *(const ulonglong2*)&kb[(c0 + 32) * KSTRIDE + dd];
            #pragma unroll
            for (int i = 0; i < 8; i++) {
                ulonglong2 qv = *(const ulonglong2*)&qs[(qrow0 + i) * D + db + dd];
                acc2[i][0] = fma2(qv.x, kv0.x, acc2[i][0]);
                acc2[i][0] = fma2(qv.y, kv0.y, acc2[i][0]);
                acc2[i][1] = fma2(qv.x, kv1.x, acc2[i][1]);
                acc2[i][1] = fma2(qv.y, kv1.y, acc2[i][1]);
            }
        }
        if (s < 3) __syncthreads();
    }

    #pragma unroll
    for (int i = 0; i < 8; i++) {
        int qrow = qbase + qrow0 + i;
        #pragma unroll
        for (int j = 0; j < 2; j++) {
            int c = cbase + c0 + j * 32;
            float lo = __uint_as_float((unsigned)(acc2[i][j] & 0xffffffffull));
            float hi = __uint_as_float((unsigned)(acc2[i][j] >> 32));
            float dot = lo + hi;
            float val = (c < count) ? fmaf(dot, INV_TAU, -g_cp[c]) : neg_inf();
            g_logits[qrow * MMAX + c] = val;
        }
    }
}

// Exact top-32 per query: fused load/transform/lvl-0 hist, 11/11/10-bit radix,
// early exit to exact in-class rank, softmax, split V gather. Last-finishing
// block resets g_count/g_done/g_bar for the next graph replay.
__global__ __launch_bounds__(1024) void topk_kernel(const float* __restrict__ Vbank,
                                                    float* __restrict__ out) {
    __shared__ unsigned su[MMAX];     // 20 KB
    __shared__ int hist[2048];        // 8 KB (aliased as gather-reduce buffer)
    __shared__ int wtot[32];
    __shared__ unsigned clsu[CLSMAX];
    __shared__ int   clsj[CLSMAX];
    __shared__ unsigned selu[TOPK];
    __shared__ int   selj[TOPK];
    __shared__ float attn[TOPK];
    __shared__ int s_b, s_above, s_cls, s_ngt, s_ncls;

    int b = blockIdx.x, t = threadIdx.x;
    int lane = t & 31, w = t >> 5;
    int count = min(g_count, MMAX);
    int cnt256 = (count + 255) & ~255;
    int n4 = cnt256 >> 2;

    for (int i = t; i < 2048; i += 1024) hist[i] = 0;
    __syncthreads();

    for (int j4b = 0; j4b < n4; j4b += 1024) {
        int j4 = j4b + t;
        bool ok = j4 < n4;
        unsigned u[4];
        if (ok) {
            float4 v = *(const float4*)&g_logits[b * MMAX + j4 * 4];
            unsigned b0 = __float_as_uint(v.x), b1 = __float_as_uint(v.y);
            unsigned b2 = __float_as_uint(v.z), b3 = __float_as_uint(v.w);
            u[0] = (b0 & 0x80000000u) ? ~b0 : (b0 | 0x80000000u);
            u[1] = (b1 & 0x80000000u) ? ~b1 : (b1 | 0x80000000u);
            u[2] = (b2 & 0x80000000u) ? ~b2 : (b2 | 0x80000000u);
            u[3] = (b3 & 0x80000000u) ? ~b3 : (b3 | 0x80000000u);
            *(uint4*)&su[j4 * 4] = make_uint4(u[0], u[1], u[2], u[3]);
        }
        #pragma unroll
        for (int e = 0; e < 4; e++) {
            unsigned act = __ballot_sync(0xffffffffu, ok);
            if (ok) {
                unsigned bin = u[e] >> 21;
                unsigned peers = __match_any_sync(act, bin);
                if (lane == (__ffs(peers) - 1))
                    atomicAdd(&hist[bin], __popc(peers));
            }
        }
    }
    __syncthreads();

    const int shifts[3] = {21, 10, 0};
    const int nbits[3]  = {11, 11, 10};
    unsigned pmask = 0, pval = 0;
    int need = TOPK;

    for (int lvl = 0; lvl < 3; lvl++) {
        int shift = shifts[lvl];
        int nb = 1 << nbits[lvl];
        unsigned bmask = (unsigned)(nb - 1);
        int bpt = (nb > 1024) ? (nb >> 10) : 1;

        if (lvl > 0) {
            for (int i = t; i < nb; i += 1024) hist[i] = 0;
            __syncthreads();
            for (int jb = 0; jb < cnt256; jb += 1024) {
                int j = jb + t;
                unsigned u = (j < cnt256) ? su[j] : 0u;
                bool ok = (j < cnt256) && ((u & pmask) == pval);
                unsigned act = __ballot_sync(0xffffffffu, ok);
                if (ok) {
                    unsigned bin = (u >> shift) & bmask;
                    unsigned peers = __match_any_sync(act, bin);
                    if (lane == (__ffs(peers) - 1))
                        atomicAdd(&hist[bin], __popc(peers));
                }
            }
            __syncthreads();
        }

        int s = 0;
        int tb = t * bpt;
        #pragma unroll 2
        for (int i = 0; i < bpt; i++)
            if (tb + i < nb) s += hist[tb + i];
        int x = s;
        #pragma unroll
        for (int o = 1; o < 32; o <<= 1) {
            int y = __shfl_down_sync(0xffffffffu, x, o);
            if (lane + o < 32) x += y;
        }
        if (lane == 0) wtot[w] = x;
        __syncthreads();
        if (t < 32) {
            int ww = wtot[t];
            int xx = ww;
            #pragma unroll
            for (int o = 1; o < 32; o <<= 1) {
                int y = __shfl_down_sync(0xffffffffu, xx, o);
                if (t + o < 32) xx += y;
            }
            wtot[t] = xx - ww;
        }
        __syncthreads();
        int S = x + wtot[w];
        int Snext = S - s;

        if (S >= need && Snext < need) {
            int c = Snext;
            int bb = tb + bpt - 1;
            while (c + hist[bb] < need) { c += hist[bb]; bb--; }
            s_b = bb; s_above = c; s_cls = hist[bb];
        }
        __syncthreads();
        pval  |= ((unsigned)s_b) << shift;
        pmask |= bmask << shift;
        need  -= s_above;
        if (s_cls <= CLSMAX) break;
        __syncthreads();
    }

    if (t == 0) { s_ngt = 0; s_ncls = 0; }
    __syncthreads();
    for (int j = t; j < cnt256; j += 1024) {
        unsigned u = su[j];
        unsigned m = u & pmask;
        if (m > pval) {
            int p = atomicAdd(&s_ngt, 1);
            selu[p] = u; selj[p] = j;
        } else if (m == pval) {
            int p = atomicAdd(&s_ncls, 1);
            if (p < CLSMAX) { clsu[p] = u; clsj[p] = j; }
        }
    }
    __syncthreads();

    int ngt  = s_ngt;
    int clsN = min(s_ncls, CLSMAX);
    if (t < clsN) {
        unsigned ui = clsu[t]; int ji = clsj[t];
        int rank = 0;
        for (int j = 0; j < clsN; j++) {
            unsigned uj = clsu[j]; int jj = clsj[j];
            rank += (uj > ui || (uj == ui && jj < ji)) ? 1 : 0;
        }
        if (rank < need) { selu[ngt + rank] = ui; selj[ngt + rank] = ji; }
    }
    __syncthreads();

    if (t < 32) {
        unsigned u = selu[t];
        unsigned bits = (u & 0x80000000u) ? (u ^ 0x80000000u) : ~u;
        float v = __int_as_float(bits);
        float m = v;
        #pragma unroll
        for (int o = 16; o > 0; o >>= 1) m = fmaxf(m, __shfl_xor_sync(0xffffffffu, m, o));
        float e = expf(v - m);
        float sm = e;
        #pragma unroll
        for (int o = 16; o > 0; o >>= 1) sm += __shfl_xor_sync(0xffffffffu, sm, o);
        attn[t] = e / sm;
        selj[t] = g_ci[selj[t]];
    }
    __syncthreads();

    float* red = (float*)hist;
    int kg = t >> 8, d = t & 255;
    float part = 0.0f;
    #pragma unroll
    for (int k = 0; k < 8; k++) {
        int kk = kg * 8 + k;
        part = fmaf(attn[kk], Vbank[(size_t)selj[kk] * D + d], part);
    }
    red[kg * 256 + d] = part;
    __syncthreads();
    if (t < 256)
        out[b * D + t] = (red[t] + red[256 + t]) + (red[512 + t] + red[768 + t]);
    __syncthreads();

    // last-finishing block resets counters for the next replay
    if (t == 0) {
        int ticket = atomicAdd(&g_done, 1);
        if (ticket == (int)gridDim.x - 1) { g_done = 0; g_count = 0; g_bar = 0; }
    }
}

extern "C" void kernel_launch(void* const* d_in, const int* in_sizes, int n_in,
                              void* d_out, int out_size) {
    const float* query = (const float*)d_in[0];
    const float* Kbank = (const float*)d_in[1];
    const float* Vbank = (const float*)d_in[2];
    const float* times = (const float*)d_in[3];
    const float* qtime = (const float*)d_in[4];
    float* out = (float*)d_out;

    int N = in_sizes[3];        // 500000

    static int smem_set = 0;
    int dyn_smem = (QT * D + 2 * CT * KSTRIDE) * 4 + CT * 4;
    if (!smem_set) {
        cudaFuncSetAttribute(fused_filter_logits_kernel,
                             cudaFuncAttributeMaxDynamicSharedMemorySize, dyn_smem);
        smem_set = 1;
    }

    fused_filter_logits_kernel<<<GRID1, 256, dyn_smem>>>(
        Kbank, query, (const float4*)times, qtime, N);
    topk_kernel<<<128, 1024>>>(Vbank, out);
}